// round 1
// baseline (speedup 1.0000x reference)
#include <cuda_runtime.h>
#include <cuda_bf16.h>
#include <cstddef>

// Problem constants
#define BB 4
#define SS 2048
#define DD 1024
#define HH 16
#define DK 64
#define MM (BB * SS)   // 8192

// Scratch: head-split intermediates [B,H,S,DK]
__device__ float g_Qh[(size_t)BB * SS * DD];
__device__ float g_Kh[(size_t)BB * SS * DD];
__device__ float g_Vh[(size_t)BB * SS * DD];
__device__ float g_Oh[(size_t)BB * SS * DD];

// ---------------------------------------------------------------------------
// GEMM: C = A @ W^T, A [M,K=1024] row-major, W [N=1024,K=1024] row-major.
// MODE 0: plain A input, head-split output  (projections)
// MODE 1: head-split A input, plain output  (final Wo projection)
// ---------------------------------------------------------------------------
#define GBM 128
#define GBN 128
#define GBK 16
#define GPAD 4

template <int MODE>
__global__ __launch_bounds__(256)
void gemm_kernel(const float* __restrict__ A, const float* __restrict__ W,
                 float* __restrict__ C)
{
    __shared__ float As[GBK][GBM + GPAD];
    __shared__ float Bs[GBK][GBN + GPAD];

    const int tid = threadIdx.x;
    const int bm = blockIdx.y * GBM;
    const int bn = blockIdx.x * GBN;
    const int tx = tid & 15;        // 0..15 -> output cols tx*8
    const int ty = tid >> 4;        // 0..15 -> output rows ty*8
    const int lrow = tid >> 2;      // 0..63
    const int lc4  = tid & 3;       // 0..3  (float4 slot along k)

    float acc[8][8];
    #pragma unroll
    for (int i = 0; i < 8; i++)
        #pragma unroll
        for (int j = 0; j < 8; j++) acc[i][j] = 0.f;

    for (int k0 = 0; k0 < DD; k0 += GBK) {
        #pragma unroll
        for (int rr = 0; rr < 2; rr++) {
            const int row = lrow + rr * 64;
            const int gk = k0 + lc4 * 4;
            // A tile
            float4 av;
            if (MODE == 1) {
                const int gm = bm + row;
                const int b = gm >> 11;          // /S
                const int s = gm & (SS - 1);
                const int h = gk >> 6;           // /DK
                const int dk = gk & (DK - 1);
                av = *(const float4*)&A[((((size_t)b * HH + h) * SS + s) << 6) + dk];
            } else {
                av = *(const float4*)&A[(size_t)(bm + row) * DD + gk];
            }
            As[lc4 * 4 + 0][row] = av.x;
            As[lc4 * 4 + 1][row] = av.y;
            As[lc4 * 4 + 2][row] = av.z;
            As[lc4 * 4 + 3][row] = av.w;
            // W tile (always plain [N,K])
            float4 wv = *(const float4*)&W[(size_t)(bn + row) * DD + gk];
            Bs[lc4 * 4 + 0][row] = wv.x;
            Bs[lc4 * 4 + 1][row] = wv.y;
            Bs[lc4 * 4 + 2][row] = wv.z;
            Bs[lc4 * 4 + 3][row] = wv.w;
        }
        __syncthreads();

        #pragma unroll
        for (int kk = 0; kk < GBK; kk++) {
            float4 a0 = *(const float4*)&As[kk][ty * 8];
            float4 a1 = *(const float4*)&As[kk][ty * 8 + 4];
            float4 b0 = *(const float4*)&Bs[kk][tx * 8];
            float4 b1 = *(const float4*)&Bs[kk][tx * 8 + 4];
            const float af[8] = {a0.x, a0.y, a0.z, a0.w, a1.x, a1.y, a1.z, a1.w};
            const float bf[8] = {b0.x, b0.y, b0.z, b0.w, b1.x, b1.y, b1.z, b1.w};
            #pragma unroll
            for (int i = 0; i < 8; i++)
                #pragma unroll
                for (int j = 0; j < 8; j++)
                    acc[i][j] += af[i] * bf[j];
        }
        __syncthreads();
    }

    // Epilogue
    #pragma unroll
    for (int i = 0; i < 8; i++) {
        const int gm = bm + ty * 8 + i;
        const int b = gm >> 11;
        const int s = gm & (SS - 1);
        #pragma unroll
        for (int j = 0; j < 8; j++) {
            const int gn = bn + tx * 8 + j;
            if (MODE == 0) {
                const int h = gn >> 6;
                const int dk = gn & (DK - 1);
                C[((((size_t)b * HH + h) * SS + s) << 6) + dk] = acc[i][j];
            } else {
                C[(size_t)gm * DD + gn] = acc[i][j];
            }
        }
    }
}

// ---------------------------------------------------------------------------
// Causal flash attention on head-split tensors [B,H,S,DK], DK=64.
// Grid (S/64, H, B); 64 threads; 1 query row per thread.
// ---------------------------------------------------------------------------
__global__ __launch_bounds__(64)
void attn_kernel(const float* __restrict__ Qh, const float* __restrict__ Kh,
                 const float* __restrict__ Vh, float* __restrict__ Oh)
{
    __shared__ float Ks[64][64];
    __shared__ float Vs[64][64];
    __shared__ float Sc[64][64];   // Sc[kk][t]: conflict-free per-lane column

    const int t = threadIdx.x;          // query row within tile
    const int qt = blockIdx.x;          // query tile
    const int h = blockIdx.y;
    const int b = blockIdx.z;
    const size_t headoff = ((size_t)(b * HH + h)) * SS * DK;
    const float scale = 0.125f;         // 1/sqrt(64)

    // Q row in registers, pre-scaled
    float qreg[64];
    {
        const float* Qp = Qh + headoff + ((size_t)(qt * 64 + t)) * DK;
        #pragma unroll
        for (int i = 0; i < 16; i++) {
            float4 f = *(const float4*)(Qp + i * 4);
            qreg[i * 4 + 0] = f.x * scale;
            qreg[i * 4 + 1] = f.y * scale;
            qreg[i * 4 + 2] = f.z * scale;
            qreg[i * 4 + 3] = f.w * scale;
        }
    }

    float m = -1e30f, l = 0.f;
    float acc[64];
    #pragma unroll
    for (int d = 0; d < 64; d++) acc[d] = 0.f;

    for (int kb = 0; kb <= qt; kb++) {
        const float4* Kp = (const float4*)(Kh + headoff + (size_t)kb * 64 * DK);
        const float4* Vp = (const float4*)(Vh + headoff + (size_t)kb * 64 * DK);
        #pragma unroll
        for (int i = 0; i < 16; i++) {
            const int idx = t + 64 * i;
            ((float4*)Ks)[idx] = Kp[idx];
            ((float4*)Vs)[idx] = Vp[idx];
        }
        __syncthreads();

        // S = q . K^T for all 64 keys (this thread's row)
        float tmax = -1e30f;
        const bool diag = (kb == qt);
        #pragma unroll 4
        for (int kk = 0; kk < 64; kk++) {
            float s0 = 0.f, s1 = 0.f, s2 = 0.f, s3 = 0.f;
            #pragma unroll
            for (int d = 0; d < 16; d++) {
                float4 kv = *(const float4*)&Ks[kk][d * 4];
                s0 += qreg[d * 4 + 0] * kv.x;
                s1 += qreg[d * 4 + 1] * kv.y;
                s2 += qreg[d * 4 + 2] * kv.z;
                s3 += qreg[d * 4 + 3] * kv.w;
            }
            float s = (s0 + s1) + (s2 + s3);
            if (diag && kk > t) s = -1e30f;
            Sc[kk][t] = s;
            tmax = fmaxf(tmax, s);
        }

        // Online softmax rescale
        const float nm = fmaxf(m, tmax);
        const float corr = __expf(m - nm);
        l *= corr;
        #pragma unroll
        for (int d = 0; d < 64; d++) acc[d] *= corr;

        // P @ V
        #pragma unroll 2
        for (int kk = 0; kk < 64; kk++) {
            const float p = __expf(Sc[kk][t] - nm);
            l += p;
            #pragma unroll
            for (int d = 0; d < 16; d++) {
                float4 vv = *(const float4*)&Vs[kk][d * 4];
                acc[d * 4 + 0] += p * vv.x;
                acc[d * 4 + 1] += p * vv.y;
                acc[d * 4 + 2] += p * vv.z;
                acc[d * 4 + 3] += p * vv.w;
            }
        }
        m = nm;
        __syncthreads();
    }

    const float inv = 1.f / l;
    float* Op = Oh + headoff + ((size_t)(qt * 64 + t)) * DK;
    #pragma unroll
    for (int i = 0; i < 16; i++) {
        float4 o;
        o.x = acc[i * 4 + 0] * inv;
        o.y = acc[i * 4 + 1] * inv;
        o.z = acc[i * 4 + 2] * inv;
        o.w = acc[i * 4 + 3] * inv;
        *(float4*)(Op + i * 4) = o;
    }
}

// ---------------------------------------------------------------------------
extern "C" void kernel_launch(void* const* d_in, const int* in_sizes, int n_in,
                              void* d_out, int out_size)
{
    const float* q  = (const float*)d_in[0];
    const float* k  = (const float*)d_in[1];
    const float* v  = (const float*)d_in[2];
    const float* Wq = (const float*)d_in[3];
    const float* Wk = (const float*)d_in[4];
    const float* Wv = (const float*)d_in[5];
    const float* Wo = (const float*)d_in[6];
    float* out = (float*)d_out;

    void *pQ, *pK, *pV, *pO;
    cudaGetSymbolAddress(&pQ, g_Qh);
    cudaGetSymbolAddress(&pK, g_Kh);
    cudaGetSymbolAddress(&pV, g_Vh);
    cudaGetSymbolAddress(&pO, g_Oh);

    dim3 gemm_grid(DD / GBN, MM / GBM);   // (8, 64)

    gemm_kernel<0><<<gemm_grid, 256>>>(q, Wq, (float*)pQ);
    gemm_kernel<0><<<gemm_grid, 256>>>(k, Wk, (float*)pK);
    gemm_kernel<0><<<gemm_grid, 256>>>(v, Wv, (float*)pV);

    dim3 attn_grid(SS / 64, HH, BB);      // (32, 16, 4)
    attn_kernel<<<attn_grid, 64>>>((const float*)pQ, (const float*)pK,
                                   (const float*)pV, (float*)pO);

    gemm_kernel<1><<<gemm_grid, 256>>>((const float*)pO, Wo, out);
}

// round 3
// speedup vs baseline: 1.6504x; 1.6504x over previous
#include <cuda_runtime.h>
#include <cuda_bf16.h>
#include <cstdint>
#include <cstddef>

// Problem constants
#define BB 4
#define SS 2048
#define DD 1024
#define HH 16
#define DK 64
#define MM (BB * SS)   // 8192

// Scratch: head-split intermediates [B,H,S,DK]
__device__ float g_Qh[(size_t)BB * SS * DD];
__device__ float g_Kh[(size_t)BB * SS * DD];
__device__ float g_Vh[(size_t)BB * SS * DD];
__device__ float g_Oh[(size_t)BB * SS * DD];

// ---------------------------------------------------------------------------
// Helpers
// ---------------------------------------------------------------------------
__device__ __forceinline__ uint32_t smem_u32(const void* p) {
    uint32_t a;
    asm("{ .reg .u64 t; cvta.to.shared.u64 t, %1; cvt.u32.u64 %0, t; }"
        : "=r"(a) : "l"(p));
    return a;
}
__device__ __forceinline__ void cp16(uint32_t saddr, const void* gptr) {
    asm volatile("cp.async.ca.shared.global [%0], [%1], 16;"
                 :: "r"(saddr), "l"(gptr) : "memory");
}
__device__ __forceinline__ void cp_commit() {
    asm volatile("cp.async.commit_group;" ::: "memory");
}
template <int N>
__device__ __forceinline__ void cp_wait() {
    asm volatile("cp.async.wait_group %0;" :: "n"(N) : "memory");
}
__device__ __forceinline__ uint32_t f2tf(float x) {
    uint32_t u;
    asm("cvt.rna.tf32.f32 %0, %1;" : "=r"(u) : "f"(x));
    return u;
}
__device__ __forceinline__ void mma_tf32(float* d, const uint32_t* a, const uint32_t* b) {
    asm volatile(
        "mma.sync.aligned.m16n8k8.row.col.f32.tf32.tf32.f32 "
        "{%0,%1,%2,%3}, {%4,%5,%6,%7}, {%8,%9}, {%0,%1,%2,%3};"
        : "+f"(d[0]), "+f"(d[1]), "+f"(d[2]), "+f"(d[3])
        : "r"(a[0]), "r"(a[1]), "r"(a[2]), "r"(a[3]), "r"(b[0]), "r"(b[1]));
}

// ---------------------------------------------------------------------------
// tf32 mma.sync GEMM: C = A @ W^T.  A [M=8192,K=1024], W [N=1024,K=1024].
// MODE 0: plain A input, head-split C output (projections)
// MODE 1: head-split A input, plain C output (Wo projection)
// Tile 128x128, BK=32, 256 threads (2x4 warps of 64x32), double-buffered cp.async.
// ---------------------------------------------------------------------------
#define RSTR 36                         // smem row stride (floats), pad 4
#define TILEF (128 * RSTR)              // 4608 floats per tile
#define SMEMF (4 * TILEF)               // 2 bufs x (A + W)
#define SMEMB (SMEMF * 4)               // 73728 bytes
#define NCHUNK (DD / 32)                // 32

template <int MODE>
__device__ __forceinline__ void issue_chunk(uint32_t sA, uint32_t sW, int it,
                                            const float* __restrict__ A,
                                            const float* __restrict__ W,
                                            int bm, int bn, int tid)
{
    const int k0 = it * 32;
    #pragma unroll
    for (int i = 0; i < 4; i++) {
        const int idx = i * 256 + tid;   // 0..1023 float4 slots
        const int r = idx >> 3;          // 0..127
        const int c4 = idx & 7;          // 0..7
        const int gk = k0 + c4 * 4;
        const float* gA;
        if (MODE == 1) {
            const int gm = bm + r;
            const int b = gm >> 11;
            const int s = gm & (SS - 1);
            const int h = gk >> 6;
            const int dk = gk & (DK - 1);
            gA = &A[((((size_t)b * HH + h) * SS + s) << 6) + dk];
        } else {
            gA = &A[(size_t)(bm + r) * DD + gk];
        }
        const uint32_t soff = (uint32_t)(r * RSTR + c4 * 4) * 4u;
        cp16(sA + soff, gA);
        cp16(sW + soff, &W[(size_t)(bn + r) * DD + gk]);
    }
    cp_commit();
}

template <int MODE>
__global__ __launch_bounds__(256)
void gemm_mma(const float* __restrict__ A, const float* __restrict__ W,
              float* __restrict__ C)
{
    extern __shared__ float smem[];
    const uint32_t sb = smem_u32(smem);
    const int tid = threadIdx.x;
    const int wid = tid >> 5;
    const int lane = tid & 31;
    const int g = lane >> 2;        // 0..7
    const int tig = lane & 3;       // 0..3
    const int wm = wid >> 2;        // 0..1  (64-row slab)
    const int wn = wid & 3;         // 0..3  (32-col slab)
    const int bm = blockIdx.y * 128;
    const int bn = blockIdx.x * 128;

    const uint32_t sA[2] = { sb, sb + 2u * TILEF * 4u };
    const uint32_t sW[2] = { sb + TILEF * 4u, sb + 3u * TILEF * 4u };
    float* fA[2] = { smem, smem + 2 * TILEF };
    float* fW[2] = { smem + TILEF, smem + 3 * TILEF };

    float acc[4][4][4];
    #pragma unroll
    for (int i = 0; i < 4; i++)
        #pragma unroll
        for (int j = 0; j < 4; j++)
            #pragma unroll
            for (int r = 0; r < 4; r++) acc[i][j][r] = 0.f;

    issue_chunk<MODE>(sA[0], sW[0], 0, A, W, bm, bn, tid);

    for (int it = 0; it < NCHUNK; ++it) {
        const int cur = it & 1;
        if (it + 1 < NCHUNK) {
            issue_chunk<MODE>(sA[cur ^ 1], sW[cur ^ 1], it + 1, A, W, bm, bn, tid);
            cp_wait<1>();
        } else {
            cp_wait<0>();
        }
        __syncthreads();

        const float* cA = fA[cur];
        const float* cW = fW[cur];
        #pragma unroll
        for (int ks = 0; ks < 4; ks++) {
            uint32_t afr[4][4], bfr[4][2];
            #pragma unroll
            for (int mt = 0; mt < 4; mt++) {
                const int row0 = wm * 64 + mt * 16 + g;
                const int kc = ks * 8 + tig;
                afr[mt][0] = f2tf(cA[row0 * RSTR + kc]);
                afr[mt][1] = f2tf(cA[(row0 + 8) * RSTR + kc]);
                afr[mt][2] = f2tf(cA[row0 * RSTR + kc + 4]);
                afr[mt][3] = f2tf(cA[(row0 + 8) * RSTR + kc + 4]);
            }
            #pragma unroll
            for (int nt = 0; nt < 4; nt++) {
                const int rowb = wn * 32 + nt * 8 + g;
                const int kc = ks * 8 + tig;
                bfr[nt][0] = f2tf(cW[rowb * RSTR + kc]);
                bfr[nt][1] = f2tf(cW[rowb * RSTR + kc + 4]);
            }
            #pragma unroll
            for (int mt = 0; mt < 4; mt++)
                #pragma unroll
                for (int nt = 0; nt < 4; nt++)
                    mma_tf32(acc[mt][nt], afr[mt], bfr[nt]);
        }
        __syncthreads();
    }

    // Epilogue: c0=C[g][2tig], c1=C[g][2tig+1], c2=C[g+8][2tig], c3=C[g+8][2tig+1]
    #pragma unroll
    for (int mt = 0; mt < 4; mt++) {
        #pragma unroll
        for (int half = 0; half < 2; half++) {
            const int gm = bm + wm * 64 + mt * 16 + g + half * 8;
            const int b = gm >> 11;
            const int s = gm & (SS - 1);
            #pragma unroll
            for (int nt = 0; nt < 4; nt++) {
                const int gn = bn + wn * 32 + nt * 8 + 2 * tig;
                float2 o;
                o.x = acc[mt][nt][half * 2 + 0];
                o.y = acc[mt][nt][half * 2 + 1];
                if (MODE == 0) {
                    const int h = gn >> 6;
                    const int dk = gn & (DK - 1);
                    *(float2*)&C[((((size_t)b * HH + h) * SS + s) << 6) + dk] = o;
                } else {
                    *(float2*)&C[(size_t)gm * DD + gn] = o;
                }
            }
        }
    }
}

// ---------------------------------------------------------------------------
// Causal flash attention on head-split tensors [B,H,S,DK], DK=64. (unchanged)
// ---------------------------------------------------------------------------
__global__ __launch_bounds__(64)
void attn_kernel(const float* __restrict__ Qh, const float* __restrict__ Kh,
                 const float* __restrict__ Vh, float* __restrict__ Oh)
{
    __shared__ float Ks[64][64];
    __shared__ float Vs[64][64];
    __shared__ float Sc[64][64];

    const int t = threadIdx.x;
    const int qt = blockIdx.x;
    const int h = blockIdx.y;
    const int b = blockIdx.z;
    const size_t headoff = ((size_t)(b * HH + h)) * SS * DK;
    const float scale = 0.125f;

    float qreg[64];
    {
        const float* Qp = Qh + headoff + ((size_t)(qt * 64 + t)) * DK;
        #pragma unroll
        for (int i = 0; i < 16; i++) {
            float4 f = *(const float4*)(Qp + i * 4);
            qreg[i * 4 + 0] = f.x * scale;
            qreg[i * 4 + 1] = f.y * scale;
            qreg[i * 4 + 2] = f.z * scale;
            qreg[i * 4 + 3] = f.w * scale;
        }
    }

    float m = -1e30f, l = 0.f;
    float acc[64];
    #pragma unroll
    for (int d = 0; d < 64; d++) acc[d] = 0.f;

    for (int kb = 0; kb <= qt; kb++) {
        const float4* Kp = (const float4*)(Kh + headoff + (size_t)kb * 64 * DK);
        const float4* Vp = (const float4*)(Vh + headoff + (size_t)kb * 64 * DK);
        #pragma unroll
        for (int i = 0; i < 16; i++) {
            const int idx = t + 64 * i;
            ((float4*)Ks)[idx] = Kp[idx];
            ((float4*)Vs)[idx] = Vp[idx];
        }
        __syncthreads();

        float tmax = -1e30f;
        const bool diag = (kb == qt);
        #pragma unroll 4
        for (int kk = 0; kk < 64; kk++) {
            float s0 = 0.f, s1 = 0.f, s2 = 0.f, s3 = 0.f;
            #pragma unroll
            for (int d = 0; d < 16; d++) {
                float4 kv = *(const float4*)&Ks[kk][d * 4];
                s0 += qreg[d * 4 + 0] * kv.x;
                s1 += qreg[d * 4 + 1] * kv.y;
                s2 += qreg[d * 4 + 2] * kv.z;
                s3 += qreg[d * 4 + 3] * kv.w;
            }
            float s = (s0 + s1) + (s2 + s3);
            if (diag && kk > t) s = -1e30f;
            Sc[kk][t] = s;
            tmax = fmaxf(tmax, s);
        }

        const float nm = fmaxf(m, tmax);
        const float corr = __expf(m - nm);
        l *= corr;
        #pragma unroll
        for (int d = 0; d < 64; d++) acc[d] *= corr;

        #pragma unroll 2
        for (int kk = 0; kk < 64; kk++) {
            const float p = __expf(Sc[kk][t] - nm);
            l += p;
            #pragma unroll
            for (int d = 0; d < 16; d++) {
                float4 vv = *(const float4*)&Vs[kk][d * 4];
                acc[d * 4 + 0] += p * vv.x;
                acc[d * 4 + 1] += p * vv.y;
                acc[d * 4 + 2] += p * vv.z;
                acc[d * 4 + 3] += p * vv.w;
            }
        }
        m = nm;
        __syncthreads();
    }

    const float inv = 1.f / l;
    float* Op = Oh + headoff + ((size_t)(qt * 64 + t)) * DK;
    #pragma unroll
    for (int i = 0; i < 16; i++) {
        float4 o;
        o.x = acc[i * 4 + 0] * inv;
        o.y = acc[i * 4 + 1] * inv;
        o.z = acc[i * 4 + 2] * inv;
        o.w = acc[i * 4 + 3] * inv;
        *(float4*)(Op + i * 4) = o;
    }
}

// ---------------------------------------------------------------------------
extern "C" void kernel_launch(void* const* d_in, const int* in_sizes, int n_in,
                              void* d_out, int out_size)
{
    const float* q  = (const float*)d_in[0];
    const float* k  = (const float*)d_in[1];
    const float* v  = (const float*)d_in[2];
    const float* Wq = (const float*)d_in[3];
    const float* Wk = (const float*)d_in[4];
    const float* Wv = (const float*)d_in[5];
    const float* Wo = (const float*)d_in[6];
    float* out = (float*)d_out;

    void *pQ, *pK, *pV, *pO;
    cudaGetSymbolAddress(&pQ, g_Qh);
    cudaGetSymbolAddress(&pK, g_Kh);
    cudaGetSymbolAddress(&pV, g_Vh);
    cudaGetSymbolAddress(&pO, g_Oh);

    cudaFuncSetAttribute(gemm_mma<0>, cudaFuncAttributeMaxDynamicSharedMemorySize, SMEMB);
    cudaFuncSetAttribute(gemm_mma<1>, cudaFuncAttributeMaxDynamicSharedMemorySize, SMEMB);

    dim3 gemm_grid(DD / 128, MM / 128);   // (8, 64)
    gemm_mma<0><<<gemm_grid, 256, SMEMB>>>(q, Wq, (float*)pQ);
    gemm_mma<0><<<gemm_grid, 256, SMEMB>>>(k, Wk, (float*)pK);
    gemm_mma<0><<<gemm_grid, 256, SMEMB>>>(v, Wv, (float*)pV);

    dim3 attn_grid(SS / 64, HH, BB);      // (32, 16, 4)
    attn_kernel<<<attn_grid, 64>>>((const float*)pQ, (const float*)pK,
                                   (const float*)pV, (float*)pO);

    gemm_mma<1><<<gemm_grid, 256, SMEMB>>>((const float*)pO, Wo, out);
}

// round 4
// speedup vs baseline: 3.5729x; 2.1649x over previous
#include <cuda_runtime.h>
#include <cuda_bf16.h>
#include <cstdint>
#include <cstddef>

// Problem constants
#define BB 4
#define SS 2048
#define DD 1024
#define HH 16
#define DK 64
#define MM (BB * SS)   // 8192

// Scratch: head-split intermediates [B,H,S,DK]
__device__ float g_Qh[(size_t)BB * SS * DD];
__device__ float g_Kh[(size_t)BB * SS * DD];
__device__ float g_Vh[(size_t)BB * SS * DD];
__device__ float g_Oh[(size_t)BB * SS * DD];

// ---------------------------------------------------------------------------
// Helpers
// ---------------------------------------------------------------------------
__device__ __forceinline__ uint32_t smem_u32(const void* p) {
    uint32_t a;
    asm("{ .reg .u64 t; cvta.to.shared.u64 t, %1; cvt.u32.u64 %0, t; }"
        : "=r"(a) : "l"(p));
    return a;
}
__device__ __forceinline__ void cp16(uint32_t saddr, const void* gptr) {
    asm volatile("cp.async.ca.shared.global [%0], [%1], 16;"
                 :: "r"(saddr), "l"(gptr) : "memory");
}
__device__ __forceinline__ void cp_commit() {
    asm volatile("cp.async.commit_group;" ::: "memory");
}
template <int N>
__device__ __forceinline__ void cp_wait() {
    asm volatile("cp.async.wait_group %0;" :: "n"(N) : "memory");
}
__device__ __forceinline__ uint32_t f2tf(float x) {
    uint32_t u;
    asm("cvt.rna.tf32.f32 %0, %1;" : "=r"(u) : "f"(x));
    return u;
}
__device__ __forceinline__ void mma_tf32(float* d, const uint32_t* a, const uint32_t* b) {
    asm volatile(
        "mma.sync.aligned.m16n8k8.row.col.f32.tf32.tf32.f32 "
        "{%0,%1,%2,%3}, {%4,%5,%6,%7}, {%8,%9}, {%0,%1,%2,%3};"
        : "+f"(d[0]), "+f"(d[1]), "+f"(d[2]), "+f"(d[3])
        : "r"(a[0]), "r"(a[1]), "r"(a[2]), "r"(a[3]), "r"(b[0]), "r"(b[1]));
}

// ---------------------------------------------------------------------------
// tf32 mma.sync GEMM: C = A @ W^T.  A [M=8192,K=1024], W [N=1024,K=1024].
// MODE 0: plain A input, head-split C output (projections)
// MODE 1: head-split A input, plain C output (Wo projection)
// ---------------------------------------------------------------------------
#define RSTR 36
#define TILEF (128 * RSTR)
#define SMEMB (4 * TILEF * 4)           // 73728 bytes
#define NCHUNK (DD / 32)                // 32

template <int MODE>
__device__ __forceinline__ void issue_chunk(uint32_t sA, uint32_t sW, int it,
                                            const float* __restrict__ A,
                                            const float* __restrict__ W,
                                            int bm, int bn, int tid)
{
    const int k0 = it * 32;
    #pragma unroll
    for (int i = 0; i < 4; i++) {
        const int idx = i * 256 + tid;
        const int r = idx >> 3;
        const int c4 = idx & 7;
        const int gk = k0 + c4 * 4;
        const float* gA;
        if (MODE == 1) {
            const int gm = bm + r;
            const int b = gm >> 11;
            const int s = gm & (SS - 1);
            const int h = gk >> 6;
            const int dk = gk & (DK - 1);
            gA = &A[((((size_t)b * HH + h) * SS + s) << 6) + dk];
        } else {
            gA = &A[(size_t)(bm + r) * DD + gk];
        }
        const uint32_t soff = (uint32_t)(r * RSTR + c4 * 4) * 4u;
        cp16(sA + soff, gA);
        cp16(sW + soff, &W[(size_t)(bn + r) * DD + gk]);
    }
    cp_commit();
}

template <int MODE>
__global__ __launch_bounds__(256)
void gemm_mma(const float* __restrict__ A, const float* __restrict__ W,
              float* __restrict__ C)
{
    extern __shared__ float smem[];
    const uint32_t sb = smem_u32(smem);
    const int tid = threadIdx.x;
    const int wid = tid >> 5;
    const int lane = tid & 31;
    const int g = lane >> 2;
    const int tig = lane & 3;
    const int wm = wid >> 2;
    const int wn = wid & 3;
    const int bm = blockIdx.y * 128;
    const int bn = blockIdx.x * 128;

    const uint32_t sA[2] = { sb, sb + 2u * TILEF * 4u };
    const uint32_t sW[2] = { sb + TILEF * 4u, sb + 3u * TILEF * 4u };
    float* fA[2] = { smem, smem + 2 * TILEF };
    float* fW[2] = { smem + TILEF, smem + 3 * TILEF };

    float acc[4][4][4];
    #pragma unroll
    for (int i = 0; i < 4; i++)
        #pragma unroll
        for (int j = 0; j < 4; j++)
            #pragma unroll
            for (int r = 0; r < 4; r++) acc[i][j][r] = 0.f;

    issue_chunk<MODE>(sA[0], sW[0], 0, A, W, bm, bn, tid);

    for (int it = 0; it < NCHUNK; ++it) {
        const int cur = it & 1;
        if (it + 1 < NCHUNK) {
            issue_chunk<MODE>(sA[cur ^ 1], sW[cur ^ 1], it + 1, A, W, bm, bn, tid);
            cp_wait<1>();
        } else {
            cp_wait<0>();
        }
        __syncthreads();

        const float* cA = fA[cur];
        const float* cW = fW[cur];
        #pragma unroll
        for (int ks = 0; ks < 4; ks++) {
            uint32_t afr[4][4], bfr[4][2];
            #pragma unroll
            for (int mt = 0; mt < 4; mt++) {
                const int row0 = wm * 64 + mt * 16 + g;
                const int kc = ks * 8 + tig;
                afr[mt][0] = f2tf(cA[row0 * RSTR + kc]);
                afr[mt][1] = f2tf(cA[(row0 + 8) * RSTR + kc]);
                afr[mt][2] = f2tf(cA[row0 * RSTR + kc + 4]);
                afr[mt][3] = f2tf(cA[(row0 + 8) * RSTR + kc + 4]);
            }
            #pragma unroll
            for (int nt = 0; nt < 4; nt++) {
                const int rowb = wn * 32 + nt * 8 + g;
                const int kc = ks * 8 + tig;
                bfr[nt][0] = f2tf(cW[rowb * RSTR + kc]);
                bfr[nt][1] = f2tf(cW[rowb * RSTR + kc + 4]);
            }
            #pragma unroll
            for (int mt = 0; mt < 4; mt++)
                #pragma unroll
                for (int nt = 0; nt < 4; nt++)
                    mma_tf32(acc[mt][nt], afr[mt], bfr[nt]);
        }
        __syncthreads();
    }

    #pragma unroll
    for (int mt = 0; mt < 4; mt++) {
        #pragma unroll
        for (int half = 0; half < 2; half++) {
            const int gm = bm + wm * 64 + mt * 16 + g + half * 8;
            const int b = gm >> 11;
            const int s = gm & (SS - 1);
            #pragma unroll
            for (int nt = 0; nt < 4; nt++) {
                const int gn = bn + wn * 32 + nt * 8 + 2 * tig;
                float2 o;
                o.x = acc[mt][nt][half * 2 + 0];
                o.y = acc[mt][nt][half * 2 + 1];
                if (MODE == 0) {
                    const int h = gn >> 6;
                    const int dk = gn & (DK - 1);
                    *(float2*)&C[((((size_t)b * HH + h) * SS + s) << 6) + dk] = o;
                } else {
                    *(float2*)&C[(size_t)gm * DD + gn] = o;
                }
            }
        }
    }
}

// ---------------------------------------------------------------------------
// Tensorized causal flash attention, head-split [B,H,S,DK], DK=64.
// CTA = 64 queries, 128 threads (4 warps x m16). Keys in 64-blocks.
// tf32 mma for QK^T and PV; C->A fragment transpose via quad shuffles.
// ---------------------------------------------------------------------------
#define QT 64
#define KT 64
#define VSTR 68

__global__ __launch_bounds__(128, 3)
void attn_mma(const float* __restrict__ Qh, const float* __restrict__ Kh,
              const float* __restrict__ Vh, float* __restrict__ Oh)
{
    __shared__ float Ks[KT][VSTR];
    __shared__ float Vs[KT][VSTR];

    const int tid = threadIdx.x;
    const int wid = tid >> 5;
    const int lane = tid & 31;
    const int g = lane >> 2;
    const int tig = lane & 3;
    const int qt = gridDim.x - 1 - blockIdx.x;   // heavy tiles first
    const int h = blockIdx.y;
    const int b = blockIdx.z;
    const size_t headoff = ((size_t)(b * HH + h)) * SS * DK;

    const int qr0 = qt * QT + wid * 16 + g;      // this thread's query rows
    const int qr1 = qr0 + 8;
    const int ql0 = wid * 16 + g;                // local (within tile)
    const int ql1 = ql0 + 8;

    // Q fragments: tf32, pre-scaled by 1/sqrt(64)
    uint32_t qf[8][4];
    {
        const float* Qp = Qh + headoff;
        #pragma unroll
        for (int ks = 0; ks < 8; ks++) {
            qf[ks][0] = f2tf(Qp[(size_t)qr0 * DK + ks * 8 + tig] * 0.125f);
            qf[ks][1] = f2tf(Qp[(size_t)qr1 * DK + ks * 8 + tig] * 0.125f);
            qf[ks][2] = f2tf(Qp[(size_t)qr0 * DK + ks * 8 + tig + 4] * 0.125f);
            qf[ks][3] = f2tf(Qp[(size_t)qr1 * DK + ks * 8 + tig + 4] * 0.125f);
        }
    }

    float oacc[8][4];
    #pragma unroll
    for (int nt = 0; nt < 8; nt++)
        #pragma unroll
        for (int r = 0; r < 4; r++) oacc[nt][r] = 0.f;
    float m0 = -1e30f, m1 = -1e30f, l0 = 0.f, l1 = 0.f;

    const uint32_t sK = smem_u32(Ks);
    const uint32_t sV = smem_u32(Vs);
    const int base = (lane & ~3) | (tig >> 1);   // shfl src for C->A transpose
    const bool odd = tig & 1;

    for (int kb = 0; kb <= qt; kb++) {
        __syncthreads();   // previous block fully consumed before overwrite
        #pragma unroll
        for (int i = 0; i < 8; i++) {
            const int idx = i * 128 + tid;       // 0..1023 float4 slots
            const int r = idx >> 4;
            const int c4 = idx & 15;
            const size_t goff = headoff + (size_t)(kb * KT + r) * DK + c4 * 4;
            const uint32_t soff = (uint32_t)(r * VSTR + c4 * 4) * 4u;
            cp16(sK + soff, Kh + goff);
            cp16(sV + soff, Vh + goff);
        }
        cp_commit();
        cp_wait<0>();
        __syncthreads();

        // ---- S = Q K^T (m16 x n64, k=64) ----
        float sacc[8][4];
        #pragma unroll
        for (int nt = 0; nt < 8; nt++)
            #pragma unroll
            for (int r = 0; r < 4; r++) sacc[nt][r] = 0.f;

        #pragma unroll
        for (int ks = 0; ks < 8; ks++) {
            #pragma unroll
            for (int nt = 0; nt < 8; nt++) {
                uint32_t bfr[2];
                bfr[0] = f2tf(Ks[nt * 8 + g][ks * 8 + tig]);
                bfr[1] = f2tf(Ks[nt * 8 + g][ks * 8 + tig + 4]);
                mma_tf32(sacc[nt], qf[ks], bfr);
            }
        }

        // ---- causal mask (diagonal block only) ----
        if (kb == qt) {
            #pragma unroll
            for (int nt = 0; nt < 8; nt++) {
                const int kc = nt * 8 + 2 * tig;
                if (kc > ql0)     sacc[nt][0] = -1e30f;
                if (kc + 1 > ql0) sacc[nt][1] = -1e30f;
                if (kc > ql1)     sacc[nt][2] = -1e30f;
                if (kc + 1 > ql1) sacc[nt][3] = -1e30f;
            }
        }

        // ---- row max (C layout + quad reduce) ----
        float tmax0 = -1e30f, tmax1 = -1e30f;
        #pragma unroll
        for (int nt = 0; nt < 8; nt++) {
            tmax0 = fmaxf(tmax0, fmaxf(sacc[nt][0], sacc[nt][1]));
            tmax1 = fmaxf(tmax1, fmaxf(sacc[nt][2], sacc[nt][3]));
        }
        tmax0 = fmaxf(tmax0, __shfl_xor_sync(0xffffffffu, tmax0, 1));
        tmax0 = fmaxf(tmax0, __shfl_xor_sync(0xffffffffu, tmax0, 2));
        tmax1 = fmaxf(tmax1, __shfl_xor_sync(0xffffffffu, tmax1, 1));
        tmax1 = fmaxf(tmax1, __shfl_xor_sync(0xffffffffu, tmax1, 2));

        const float nm0 = fmaxf(m0, tmax0);
        const float nm1 = fmaxf(m1, tmax1);
        const float corr0 = __expf(m0 - nm0);
        const float corr1 = __expf(m1 - nm1);
        l0 *= corr0;
        l1 *= corr1;
        #pragma unroll
        for (int nt = 0; nt < 8; nt++) {
            oacc[nt][0] *= corr0; oacc[nt][1] *= corr0;
            oacc[nt][2] *= corr1; oacc[nt][3] *= corr1;
        }
        m0 = nm0; m1 = nm1;

        // ---- PV: transpose S via shfl, exp, mma ----
        #pragma unroll
        for (int ks = 0; ks < 8; ks++) {
            const float s00 = __shfl_sync(0xffffffffu, sacc[ks][0], base);
            const float s01 = __shfl_sync(0xffffffffu, sacc[ks][1], base);
            const float s10 = __shfl_sync(0xffffffffu, sacc[ks][2], base);
            const float s11 = __shfl_sync(0xffffffffu, sacc[ks][3], base);
            const float t00 = __shfl_sync(0xffffffffu, sacc[ks][0], base + 2);
            const float t01 = __shfl_sync(0xffffffffu, sacc[ks][1], base + 2);
            const float t10 = __shfl_sync(0xffffffffu, sacc[ks][2], base + 2);
            const float t11 = __shfl_sync(0xffffffffu, sacc[ks][3], base + 2);
            const float p0 = __expf((odd ? s01 : s00) - nm0);   // (g,     tig)
            const float p1 = __expf((odd ? s11 : s10) - nm1);   // (g+8,   tig)
            const float p2 = __expf((odd ? t01 : t00) - nm0);   // (g,   tig+4)
            const float p3 = __expf((odd ? t11 : t10) - nm1);   // (g+8, tig+4)
            l0 += p0 + p2;
            l1 += p1 + p3;
            uint32_t af[4] = { f2tf(p0), f2tf(p1), f2tf(p2), f2tf(p3) };
            #pragma unroll
            for (int nt = 0; nt < 8; nt++) {
                uint32_t bfr[2];
                bfr[0] = f2tf(Vs[ks * 8 + tig][nt * 8 + g]);
                bfr[1] = f2tf(Vs[ks * 8 + tig + 4][nt * 8 + g]);
                mma_tf32(oacc[nt], af, bfr);
            }
        }
    }

    // final l reduction across quad
    l0 += __shfl_xor_sync(0xffffffffu, l0, 1);
    l0 += __shfl_xor_sync(0xffffffffu, l0, 2);
    l1 += __shfl_xor_sync(0xffffffffu, l1, 1);
    l1 += __shfl_xor_sync(0xffffffffu, l1, 2);
    const float inv0 = 1.f / l0;
    const float inv1 = 1.f / l1;

    #pragma unroll
    for (int nt = 0; nt < 8; nt++) {
        const int d = nt * 8 + 2 * tig;
        float2 o0, o1;
        o0.x = oacc[nt][0] * inv0; o0.y = oacc[nt][1] * inv0;
        o1.x = oacc[nt][2] * inv1; o1.y = oacc[nt][3] * inv1;
        *(float2*)&Oh[headoff + (size_t)qr0 * DK + d] = o0;
        *(float2*)&Oh[headoff + (size_t)qr1 * DK + d] = o1;
    }
}

// ---------------------------------------------------------------------------
extern "C" void kernel_launch(void* const* d_in, const int* in_sizes, int n_in,
                              void* d_out, int out_size)
{
    const float* q  = (const float*)d_in[0];
    const float* k  = (const float*)d_in[1];
    const float* v  = (const float*)d_in[2];
    const float* Wq = (const float*)d_in[3];
    const float* Wk = (const float*)d_in[4];
    const float* Wv = (const float*)d_in[5];
    const float* Wo = (const float*)d_in[6];
    float* out = (float*)d_out;

    void *pQ, *pK, *pV, *pO;
    cudaGetSymbolAddress(&pQ, g_Qh);
    cudaGetSymbolAddress(&pK, g_Kh);
    cudaGetSymbolAddress(&pV, g_Vh);
    cudaGetSymbolAddress(&pO, g_Oh);

    cudaFuncSetAttribute(gemm_mma<0>, cudaFuncAttributeMaxDynamicSharedMemorySize, SMEMB);
    cudaFuncSetAttribute(gemm_mma<1>, cudaFuncAttributeMaxDynamicSharedMemorySize, SMEMB);

    dim3 gemm_grid(DD / 128, MM / 128);   // (8, 64)
    gemm_mma<0><<<gemm_grid, 256, SMEMB>>>(q, Wq, (float*)pQ);
    gemm_mma<0><<<gemm_grid, 256, SMEMB>>>(k, Wk, (float*)pK);
    gemm_mma<0><<<gemm_grid, 256, SMEMB>>>(v, Wv, (float*)pV);

    dim3 attn_grid(SS / QT, HH, BB);      // (32, 16, 4)
    attn_mma<<<attn_grid, 128>>>((const float*)pQ, (const float*)pK,
                                 (const float*)pV, (float*)pO);

    gemm_mma<1><<<gemm_grid, 256, SMEMB>>>((const float*)pO, Wo, out);
}

// round 5
// speedup vs baseline: 4.7343x; 1.3250x over previous
#include <cuda_runtime.h>
#include <cstdint>
#include <cstddef>

// Problem constants
#define BB 4
#define SS 2048
#define DD 1024
#define HH 16
#define DK 64
#define MM (BB * SS)   // 8192

// Scratch
__device__ float g_qc[(size_t)MM * DD];
__device__ float g_kc[(size_t)MM * DD];
__device__ float g_vc[(size_t)MM * DD];
__device__ float g_Wqc[DD * DD];
__device__ float g_Wkc[DD * DD];
__device__ float g_Wvc[DD * DD];
__device__ float g_Woc[DD * DD];
__device__ float g_Qh[(size_t)MM * DD];   // [B,H,S,DK] tf32
__device__ float g_Kh[(size_t)MM * DD];   // [B,H,S,DK] tf32
__device__ float g_Vt[(size_t)MM * DD];   // [B,H,DK,S] tf32
__device__ float g_Oh[(size_t)MM * DD];   // [B,H,S,DK] tf32

// ---------------------------------------------------------------------------
// Helpers
// ---------------------------------------------------------------------------
__device__ __forceinline__ uint32_t smem_u32(const void* p) {
    uint32_t a;
    asm("{ .reg .u64 t; cvta.to.shared.u64 t, %1; cvt.u32.u64 %0, t; }"
        : "=r"(a) : "l"(p));
    return a;
}
__device__ __forceinline__ void cp16(uint32_t saddr, const void* gptr) {
    asm volatile("cp.async.ca.shared.global [%0], [%1], 16;"
                 :: "r"(saddr), "l"(gptr) : "memory");
}
__device__ __forceinline__ void cp_commit() {
    asm volatile("cp.async.commit_group;" ::: "memory");
}
template <int N>
__device__ __forceinline__ void cp_wait() {
    asm volatile("cp.async.wait_group %0;" :: "n"(N) : "memory");
}
__device__ __forceinline__ uint32_t f2tf(float x) {
    uint32_t u;
    asm("cvt.rna.tf32.f32 %0, %1;" : "=r"(u) : "f"(x));
    return u;
}
__device__ __forceinline__ void mma_tf32(float* d, const uint32_t* a, const uint32_t* b) {
    asm volatile(
        "mma.sync.aligned.m16n8k8.row.col.f32.tf32.tf32.f32 "
        "{%0,%1,%2,%3}, {%4,%5,%6,%7}, {%8,%9}, {%0,%1,%2,%3};"
        : "+f"(d[0]), "+f"(d[1]), "+f"(d[2]), "+f"(d[3])
        : "r"(a[0]), "r"(a[1]), "r"(a[2]), "r"(a[3]), "r"(b[0]), "r"(b[1]));
}
__device__ __forceinline__ void ldsm4(uint32_t* r, uint32_t addr) {
    asm volatile("ldmatrix.sync.aligned.m8n8.x4.shared.b16 {%0,%1,%2,%3}, [%4];"
                 : "=r"(r[0]), "=r"(r[1]), "=r"(r[2]), "=r"(r[3]) : "r"(addr));
}

// ---------------------------------------------------------------------------
// Pre-pass: round an fp32 array to tf32-nearest in place of a copy
// ---------------------------------------------------------------------------
__global__ __launch_bounds__(256)
void round_tf32(const float4* __restrict__ src, float4* __restrict__ dst, int n4)
{
    const int i = blockIdx.x * blockDim.x + threadIdx.x;
    if (i < n4) {
        float4 v = src[i];
        asm("cvt.rna.tf32.f32 %0, %0;" : "+f"(v.x));
        asm("cvt.rna.tf32.f32 %0, %0;" : "+f"(v.y));
        asm("cvt.rna.tf32.f32 %0, %0;" : "+f"(v.z));
        asm("cvt.rna.tf32.f32 %0, %0;" : "+f"(v.w));
        dst[i] = v;
    }
}

// ---------------------------------------------------------------------------
// tf32 mma.sync GEMM core: C = A @ W^T, tile 128x128, BK=32, 256 threads.
// Inputs already tf32-rounded. Fragments via ldmatrix.x4.
// ---------------------------------------------------------------------------
#define RSTR 36
#define TILEF (128 * RSTR)
#define GSMEM (4 * TILEF * 4)    // 73728 bytes
#define NCHUNK (DD / 32)         // 32

template <bool GATHER>
__device__ __forceinline__ void issue_chunk(uint32_t sA, uint32_t sW, int it,
                                            const float* __restrict__ A,
                                            const float* __restrict__ W,
                                            int bm, int bn, int tid)
{
    const int k0 = it * 32;
    #pragma unroll
    for (int i = 0; i < 4; i++) {
        const int idx = i * 256 + tid;
        const int r = idx >> 3;
        const int c4 = idx & 7;
        const int gk = k0 + c4 * 4;
        const float* gA;
        if (GATHER) {
            const int gm = bm + r;
            const int b = gm >> 11;
            const int s = gm & (SS - 1);
            const int h = gk >> 6;
            const int dk = gk & (DK - 1);
            gA = &A[((((size_t)b * HH + h) * SS + s) << 6) + dk];
        } else {
            gA = &A[(size_t)(bm + r) * DD + gk];
        }
        const uint32_t soff = (uint32_t)(r * RSTR + c4 * 4) * 4u;
        cp16(sA + soff, gA);
        cp16(sW + soff, &W[(size_t)(bn + r) * DD + gk]);
    }
    cp_commit();
}

template <bool GATHER>
__device__ __forceinline__ void gemm_core(const float* __restrict__ A,
                                          const float* __restrict__ W,
                                          float (&acc)[4][4][4],
                                          int bm, int bn, char* smem)
{
    const uint32_t sb = smem_u32(smem);
    const int tid = threadIdx.x;
    const int lane = tid & 31;
    const int wid = tid >> 5;
    const int wm = wid >> 2;
    const int wn = wid & 3;
    const int tr = lane & 7;
    const int qd = lane >> 3;

    // ldmatrix per-thread base offsets (bytes) within a tile
    const uint32_t aoff = (uint32_t)((wm * 64 + (qd & 1) * 8 + tr) * RSTR + (qd >> 1) * 4) * 4u;
    const uint32_t boff = (uint32_t)((wn * 32 + (qd >> 1) * 8 + tr) * RSTR + (qd & 1) * 4) * 4u;

    const uint32_t sA[2] = { sb, sb + 2u * TILEF * 4u };
    const uint32_t sW[2] = { sb + TILEF * 4u, sb + 3u * TILEF * 4u };

    issue_chunk<GATHER>(sA[0], sW[0], 0, A, W, bm, bn, tid);

    for (int it = 0; it < NCHUNK; ++it) {
        const int cur = it & 1;
        if (it + 1 < NCHUNK) {
            issue_chunk<GATHER>(sA[cur ^ 1], sW[cur ^ 1], it + 1, A, W, bm, bn, tid);
            cp_wait<1>();
        } else {
            cp_wait<0>();
        }
        __syncthreads();

        const uint32_t aT = sA[cur] + aoff;
        const uint32_t bT = sW[cur] + boff;
        #pragma unroll
        for (int ks = 0; ks < 4; ks++) {
            uint32_t afr[4][4], bfr[4][2];
            #pragma unroll
            for (int mt = 0; mt < 4; mt++)
                ldsm4(afr[mt], aT + (uint32_t)(mt * 16 * RSTR) * 4u + (uint32_t)ks * 32u);
            #pragma unroll
            for (int p = 0; p < 2; p++) {
                uint32_t r4[4];
                ldsm4(r4, bT + (uint32_t)(p * 16 * RSTR) * 4u + (uint32_t)ks * 32u);
                bfr[2 * p][0] = r4[0]; bfr[2 * p][1] = r4[1];
                bfr[2 * p + 1][0] = r4[2]; bfr[2 * p + 1][1] = r4[3];
            }
            #pragma unroll
            for (int mt = 0; mt < 4; mt++)
                #pragma unroll
                for (int nt = 0; nt < 4; nt++)
                    mma_tf32(acc[mt][nt], afr[mt], bfr[nt]);
        }
        __syncthreads();
    }
}

// Fused Q/K/V projections: grid (8, 64, 3). z=0 -> Qh, z=1 -> Kh, z=2 -> Vt.
__global__ __launch_bounds__(256, 2)
void gemm_qkv(const float* __restrict__ A0, const float* __restrict__ A1,
              const float* __restrict__ A2,
              const float* __restrict__ W0, const float* __restrict__ W1,
              const float* __restrict__ W2,
              float* __restrict__ C0, float* __restrict__ C1,
              float* __restrict__ C2)
{
    extern __shared__ char smem[];
    const int z = blockIdx.z;
    const float* A = (z == 0) ? A0 : (z == 1) ? A1 : A2;
    const float* W = (z == 0) ? W0 : (z == 1) ? W1 : W2;
    float* C = (z == 0) ? C0 : (z == 1) ? C1 : C2;
    const int bm = blockIdx.y * 128;
    const int bn = blockIdx.x * 128;

    float acc[4][4][4];
    #pragma unroll
    for (int i = 0; i < 4; i++)
        #pragma unroll
        for (int j = 0; j < 4; j++)
            #pragma unroll
            for (int r = 0; r < 4; r++) acc[i][j][r] = 0.f;

    gemm_core<false>(A, W, acc, bm, bn, smem);

    const int lane = threadIdx.x & 31;
    const int wid = threadIdx.x >> 5;
    const int g = lane >> 2;
    const int tig = lane & 3;
    const int wm = wid >> 2;
    const int wn = wid & 3;

    #pragma unroll
    for (int mt = 0; mt < 4; mt++) {
        #pragma unroll
        for (int half = 0; half < 2; half++) {
            const int gm = bm + wm * 64 + mt * 16 + g + half * 8;
            const int b = gm >> 11;
            const int s = gm & (SS - 1);
            #pragma unroll
            for (int nt = 0; nt < 4; nt++) {
                const int gn = bn + wn * 32 + nt * 8 + 2 * tig;
                const float vx = __uint_as_float(f2tf(acc[mt][nt][half * 2 + 0]));
                const float vy = __uint_as_float(f2tf(acc[mt][nt][half * 2 + 1]));
                const int h = gn >> 6;
                const int dk = gn & (DK - 1);
                if (z < 2) {
                    float2 o; o.x = vx; o.y = vy;
                    *(float2*)&C[((((size_t)b * HH + h) * SS + s) << 6) + dk] = o;
                } else {
                    // transposed scatter: Vt[b][h][dk][s]
                    const size_t base = (((size_t)b * HH + h) * DK);
                    C[(base + dk) * SS + s] = vx;
                    C[(base + dk + 1) * SS + s] = vy;
                }
            }
        }
    }
}

// Output projection: gather-A from head-split Oh, plain fp32 epilogue.
__global__ __launch_bounds__(256, 2)
void gemm_o(const float* __restrict__ A, const float* __restrict__ W,
            float* __restrict__ C)
{
    extern __shared__ char smem[];
    const int bm = blockIdx.y * 128;
    const int bn = blockIdx.x * 128;

    float acc[4][4][4];
    #pragma unroll
    for (int i = 0; i < 4; i++)
        #pragma unroll
        for (int j = 0; j < 4; j++)
            #pragma unroll
            for (int r = 0; r < 4; r++) acc[i][j][r] = 0.f;

    gemm_core<true>(A, W, acc, bm, bn, smem);

    const int lane = threadIdx.x & 31;
    const int wid = threadIdx.x >> 5;
    const int g = lane >> 2;
    const int tig = lane & 3;
    const int wm = wid >> 2;
    const int wn = wid & 3;

    #pragma unroll
    for (int mt = 0; mt < 4; mt++) {
        #pragma unroll
        for (int half = 0; half < 2; half++) {
            const int gm = bm + wm * 64 + mt * 16 + g + half * 8;
            #pragma unroll
            for (int nt = 0; nt < 4; nt++) {
                const int gn = bn + wn * 32 + nt * 8 + 2 * tig;
                float2 o;
                o.x = acc[mt][nt][half * 2 + 0];
                o.y = acc[mt][nt][half * 2 + 1];
                *(float2*)&C[(size_t)gm * DD + gn] = o;
            }
        }
    }
}

// ---------------------------------------------------------------------------
// Tensorized causal flash attention.
// Qh/Kh [B,H,S,DK] tf32; Vt [B,H,DK,S] tf32. CTA = 64 queries, 128 threads.
// Double-buffered cp.async staging; all fragments via ldmatrix.
// ---------------------------------------------------------------------------
#define QT 64
#define AST 68
#define ATILE (64 * AST)               // floats per tile
#define ASMEM (4 * ATILE * 4)          // 69632 bytes

__device__ __forceinline__ void attn_stage(uint32_t sK, uint32_t sV,
                                           const float* __restrict__ Kh,
                                           const float* __restrict__ Vt,
                                           size_t headoff, int kb, int tid)
{
    #pragma unroll
    for (int i = 0; i < 8; i++) {
        const int idx = i * 128 + tid;
        const int r = idx >> 4;          // K: key row | V: d row
        const int c4 = idx & 15;
        const uint32_t soff = (uint32_t)(r * AST + c4 * 4) * 4u;
        cp16(sK + soff, &Kh[headoff + (size_t)(kb * 64 + r) * DK + c4 * 4]);
        cp16(sV + soff, &Vt[headoff + (size_t)r * SS + kb * 64 + c4 * 4]);
    }
    cp_commit();
}

__global__ __launch_bounds__(128, 3)
void attn_mma(const float* __restrict__ Qh, const float* __restrict__ Kh,
              const float* __restrict__ Vt, float* __restrict__ Oh)
{
    extern __shared__ float sm[];
    const uint32_t sb = smem_u32(sm);
    const uint32_t sK[2] = { sb, sb + (uint32_t)ATILE * 4u };
    const uint32_t sV[2] = { sb + 2u * ATILE * 4u, sb + 3u * ATILE * 4u };

    const int tid = threadIdx.x;
    const int wid = tid >> 5;
    const int lane = tid & 31;
    const int g = lane >> 2;
    const int tig = lane & 3;
    const int tr = lane & 7;
    const int qd = lane >> 3;
    const int qt = gridDim.x - 1 - blockIdx.x;   // heavy tiles first
    const int h = blockIdx.y;
    const int b = blockIdx.z;
    const size_t headoff = ((size_t)(b * HH + h)) * SS * DK;

    // Stage Q tile into sK[1]; stage kb=0 K/V into buf 0 (one group).
    #pragma unroll
    for (int i = 0; i < 8; i++) {
        const int idx = i * 128 + tid;
        const int r = idx >> 4;
        const int c4 = idx & 15;
        cp16(sK[1] + (uint32_t)(r * AST + c4 * 4) * 4u,
             &Qh[headoff + (size_t)(qt * QT + r) * DK + c4 * 4]);
    }
    attn_stage(sK[0], sV[0], Kh, Vt, headoff, 0, tid);   // commits the group
    cp_wait<0>();
    __syncthreads();

    // Q fragments via ldmatrix (rows = this warp's 16 queries), scale by 1/8.
    uint32_t qf[8][4];
    {
        const uint32_t qbase = sK[1]
            + (uint32_t)((wid * 16 + (qd & 1) * 8 + tr) * AST + (qd >> 1) * 4) * 4u;
        #pragma unroll
        for (int ks = 0; ks < 8; ks++) {
            ldsm4(qf[ks], qbase + (uint32_t)ks * 32u);
            #pragma unroll
            for (int j = 0; j < 4; j++)
                qf[ks][j] = __float_as_uint(__uint_as_float(qf[ks][j]) * 0.125f);
        }
    }
    __syncthreads();   // all qf reads done before buf1 is re-staged

    const int ql0 = wid * 16 + g;
    const int ql1 = ql0 + 8;
    // B-fragment ldmatrix base offset (bytes), shared by K and V tiles
    const uint32_t foff = (uint32_t)(((qd >> 1) * 8 + tr) * AST + (qd & 1) * 4) * 4u;

    float oacc[8][4];
    #pragma unroll
    for (int nt = 0; nt < 8; nt++)
        #pragma unroll
        for (int r = 0; r < 4; r++) oacc[nt][r] = 0.f;
    float m0 = -1e30f, m1 = -1e30f, l0 = 0.f, l1 = 0.f;

    const int base = (lane & ~3) | (tig >> 1);
    const bool odd = tig & 1;

    for (int kb = 0; kb <= qt; kb++) {
        const int cur = kb & 1;
        if (kb < qt) {
            attn_stage(sK[cur ^ 1], sV[cur ^ 1], Kh, Vt, headoff, kb + 1, tid);
            cp_wait<1>();
        } else {
            cp_wait<0>();
        }
        __syncthreads();

        // ---- S = Q K^T ----
        float sacc[8][4];
        #pragma unroll
        for (int nt = 0; nt < 8; nt++)
            #pragma unroll
            for (int r = 0; r < 4; r++) sacc[nt][r] = 0.f;

        const uint32_t kT = sK[cur] + foff;
        #pragma unroll
        for (int ks = 0; ks < 8; ks++) {
            uint32_t bfr[8][2];
            #pragma unroll
            for (int p = 0; p < 4; p++) {
                uint32_t r4[4];
                ldsm4(r4, kT + (uint32_t)(p * 16 * AST) * 4u + (uint32_t)ks * 32u);
                bfr[2 * p][0] = r4[0]; bfr[2 * p][1] = r4[1];
                bfr[2 * p + 1][0] = r4[2]; bfr[2 * p + 1][1] = r4[3];
            }
            #pragma unroll
            for (int nt = 0; nt < 8; nt++)
                mma_tf32(sacc[nt], qf[ks], bfr[nt]);
        }

        // ---- causal mask (diagonal block only) ----
        if (kb == qt) {
            #pragma unroll
            for (int nt = 0; nt < 8; nt++) {
                const int kc = nt * 8 + 2 * tig;
                if (kc > ql0)     sacc[nt][0] = -1e30f;
                if (kc + 1 > ql0) sacc[nt][1] = -1e30f;
                if (kc > ql1)     sacc[nt][2] = -1e30f;
                if (kc + 1 > ql1) sacc[nt][3] = -1e30f;
            }
        }

        // ---- row max + online softmax bookkeeping ----
        float tmax0 = -1e30f, tmax1 = -1e30f;
        #pragma unroll
        for (int nt = 0; nt < 8; nt++) {
            tmax0 = fmaxf(tmax0, fmaxf(sacc[nt][0], sacc[nt][1]));
            tmax1 = fmaxf(tmax1, fmaxf(sacc[nt][2], sacc[nt][3]));
        }
        tmax0 = fmaxf(tmax0, __shfl_xor_sync(0xffffffffu, tmax0, 1));
        tmax0 = fmaxf(tmax0, __shfl_xor_sync(0xffffffffu, tmax0, 2));
        tmax1 = fmaxf(tmax1, __shfl_xor_sync(0xffffffffu, tmax1, 1));
        tmax1 = fmaxf(tmax1, __shfl_xor_sync(0xffffffffu, tmax1, 2));

        const float nm0 = fmaxf(m0, tmax0);
        const float nm1 = fmaxf(m1, tmax1);
        const float corr0 = __expf(m0 - nm0);
        const float corr1 = __expf(m1 - nm1);
        l0 *= corr0;
        l1 *= corr1;
        #pragma unroll
        for (int nt = 0; nt < 8; nt++) {
            oacc[nt][0] *= corr0; oacc[nt][1] *= corr0;
            oacc[nt][2] *= corr1; oacc[nt][3] *= corr1;
        }
        m0 = nm0; m1 = nm1;

        // ---- PV: transpose S via shfl, exp, mma ----
        const uint32_t vT = sV[cur] + foff;
        #pragma unroll
        for (int ks = 0; ks < 8; ks++) {
            const float s00 = __shfl_sync(0xffffffffu, sacc[ks][0], base);
            const float s01 = __shfl_sync(0xffffffffu, sacc[ks][1], base);
            const float s10 = __shfl_sync(0xffffffffu, sacc[ks][2], base);
            const float s11 = __shfl_sync(0xffffffffu, sacc[ks][3], base);
            const float t00 = __shfl_sync(0xffffffffu, sacc[ks][0], base + 2);
            const float t01 = __shfl_sync(0xffffffffu, sacc[ks][1], base + 2);
            const float t10 = __shfl_sync(0xffffffffu, sacc[ks][2], base + 2);
            const float t11 = __shfl_sync(0xffffffffu, sacc[ks][3], base + 2);
            const float p0 = __expf((odd ? s01 : s00) - nm0);
            const float p1 = __expf((odd ? s11 : s10) - nm1);
            const float p2 = __expf((odd ? t01 : t00) - nm0);
            const float p3 = __expf((odd ? t11 : t10) - nm1);
            l0 += p0 + p2;
            l1 += p1 + p3;
            uint32_t af[4] = { f2tf(p0), f2tf(p1), f2tf(p2), f2tf(p3) };
            uint32_t bfr[8][2];
            #pragma unroll
            for (int p = 0; p < 4; p++) {
                uint32_t r4[4];
                ldsm4(r4, vT + (uint32_t)(p * 16 * AST) * 4u + (uint32_t)ks * 32u);
                bfr[2 * p][0] = r4[0]; bfr[2 * p][1] = r4[1];
                bfr[2 * p + 1][0] = r4[2]; bfr[2 * p + 1][1] = r4[3];
            }
            #pragma unroll
            for (int nt = 0; nt < 8; nt++)
                mma_tf32(oacc[nt], af, bfr[nt]);
        }
        __syncthreads();   // everyone done with buf[cur] before it is restaged
    }

    l0 += __shfl_xor_sync(0xffffffffu, l0, 1);
    l0 += __shfl_xor_sync(0xffffffffu, l0, 2);
    l1 += __shfl_xor_sync(0xffffffffu, l1, 1);
    l1 += __shfl_xor_sync(0xffffffffu, l1, 2);
    const float inv0 = 1.f / l0;
    const float inv1 = 1.f / l1;

    const int qr0 = qt * QT + wid * 16 + g;
    const int qr1 = qr0 + 8;
    #pragma unroll
    for (int nt = 0; nt < 8; nt++) {
        const int d = nt * 8 + 2 * tig;
        float2 o0, o1;   // tf32-rounded: consumed by the Wo GEMM
        o0.x = __uint_as_float(f2tf(oacc[nt][0] * inv0));
        o0.y = __uint_as_float(f2tf(oacc[nt][1] * inv0));
        o1.x = __uint_as_float(f2tf(oacc[nt][2] * inv1));
        o1.y = __uint_as_float(f2tf(oacc[nt][3] * inv1));
        *(float2*)&Oh[headoff + (size_t)qr0 * DK + d] = o0;
        *(float2*)&Oh[headoff + (size_t)qr1 * DK + d] = o1;
    }
}

// ---------------------------------------------------------------------------
extern "C" void kernel_launch(void* const* d_in, const int* in_sizes, int n_in,
                              void* d_out, int out_size)
{
    const float* q  = (const float*)d_in[0];
    const float* k  = (const float*)d_in[1];
    const float* v  = (const float*)d_in[2];
    const float* Wq = (const float*)d_in[3];
    const float* Wk = (const float*)d_in[4];
    const float* Wv = (const float*)d_in[5];
    const float* Wo = (const float*)d_in[6];
    float* out = (float*)d_out;

    void *pqc, *pkc, *pvc, *pWq, *pWk, *pWv, *pWo, *pQ, *pK, *pVt, *pO;
    cudaGetSymbolAddress(&pqc, g_qc);
    cudaGetSymbolAddress(&pkc, g_kc);
    cudaGetSymbolAddress(&pvc, g_vc);
    cudaGetSymbolAddress(&pWq, g_Wqc);
    cudaGetSymbolAddress(&pWk, g_Wkc);
    cudaGetSymbolAddress(&pWv, g_Wvc);
    cudaGetSymbolAddress(&pWo, g_Woc);
    cudaGetSymbolAddress(&pQ, g_Qh);
    cudaGetSymbolAddress(&pK, g_Kh);
    cudaGetSymbolAddress(&pVt, g_Vt);
    cudaGetSymbolAddress(&pO, g_Oh);

    cudaFuncSetAttribute(gemm_qkv, cudaFuncAttributeMaxDynamicSharedMemorySize, GSMEM);
    cudaFuncSetAttribute(gemm_o, cudaFuncAttributeMaxDynamicSharedMemorySize, GSMEM);
    cudaFuncSetAttribute(attn_mma, cudaFuncAttributeMaxDynamicSharedMemorySize, ASMEM);

    // Pre-pass: tf32-round inputs and weights
    const int nbig4 = (int)((size_t)MM * DD / 4);   // 2097152
    const int nw4 = DD * DD / 4;                    // 262144
    round_tf32<<<nbig4 / 256, 256>>>((const float4*)q, (float4*)pqc, nbig4);
    round_tf32<<<nbig4 / 256, 256>>>((const float4*)k, (float4*)pkc, nbig4);
    round_tf32<<<nbig4 / 256, 256>>>((const float4*)v, (float4*)pvc, nbig4);
    round_tf32<<<nw4 / 256, 256>>>((const float4*)Wq, (float4*)pWq, nw4);
    round_tf32<<<nw4 / 256, 256>>>((const float4*)Wk, (float4*)pWk, nw4);
    round_tf32<<<nw4 / 256, 256>>>((const float4*)Wv, (float4*)pWv, nw4);
    round_tf32<<<nw4 / 256, 256>>>((const float4*)Wo, (float4*)pWo, nw4);

    // Fused Q/K/V projections
    dim3 qkv_grid(DD / 128, MM / 128, 3);   // (8, 64, 3)
    gemm_qkv<<<qkv_grid, 256, GSMEM>>>(
        (const float*)pqc, (const float*)pkc, (const float*)pvc,
        (const float*)pWq, (const float*)pWk, (const float*)pWv,
        (float*)pQ, (float*)pK, (float*)pVt);

    // Attention
    dim3 attn_grid(SS / QT, HH, BB);        // (32, 16, 4)
    attn_mma<<<attn_grid, 128, ASMEM>>>((const float*)pQ, (const float*)pK,
                                        (const float*)pVt, (float*)pO);

    // Output projection
    dim3 o_grid(DD / 128, MM / 128);        // (8, 64)
    gemm_o<<<o_grid, 256, GSMEM>>>((const float*)pO, (const float*)pWo, out);
}